// round 6
// baseline (speedup 1.0000x reference)
#include <cuda_runtime.h>
#include <cuda_fp16.h>

// InstHead fused. R6: pass1 computes h GEMM (3-term tf32) + mask GEMM (2-term)
// + stats + pooled, and spills h as fp16 (fragment-layout, coalesced) to a
// device-global scratch. pass2 is a pure streaming kernel: BN affine + ReLU +
// 32x3 projection from the fp16 h buffer. feats read once.

#define C 32
#define WPB 4
typedef unsigned int u32;

__device__ __forceinline__ u32 f2tf(float x) {
    u32 r; asm("cvt.rna.tf32.f32 %0, %1;" : "=r"(r) : "f"(x)); return r;
}
__device__ __forceinline__ void split_tf(float x, u32& hi, u32& lo) {
    hi = f2tf(x);
    lo = f2tf(x - __uint_as_float(hi));
}

#define MMA(d0,d1,d2,d3,a0,a1,a2,a3,b0,b1) \
    asm("mma.sync.aligned.m16n8k8.row.col.f32.tf32.tf32.f32 " \
        "{%0,%1,%2,%3}, {%4,%5,%6,%7}, {%8,%9}, {%0,%1,%2,%3};" \
        : "+f"(d0), "+f"(d1), "+f"(d2), "+f"(d3) \
        : "r"(a0), "r"(a1), "r"(a2), "r"(a3), "r"(b0), "r"(b1))

// ---- scratch ----
__device__ float g_pool[64 * C];
__device__ float g_cnt[64];
__device__ float g_sumH[C];
__device__ float g_sumH2[C];
__device__ float g_bns[C];   // BN scale  (gamma / std)
__device__ float g_bnt[C];   // BN shift  (beta - mu*scale)
// h scratch: fp16 pairs, fragment layout, 512 u32 per 32-point tile.
// capacity: 70000 tiles = 2.24M points -> 35.84M u32 (143 MB)
#define HCAP_TILES 70000
__device__ u32 g_h[HCAP_TILES * 512];

__global__ void zero_kernel(int B) {
    int t = threadIdx.x;
    for (int i = t; i < B * C; i += blockDim.x) g_pool[i] = 0.f;
    if (t < B) g_cnt[t] = 0.f;
    if (t < C) { g_sumH[t] = 0.f; g_sumH2[t] = 0.f; }
}

#define XP 36
#define TP 32
#define CH(i, tg) (((i) >> 1) * 8 + 2 * (tg) + ((i) & 1))

// ================= PASS 1 =================
__global__ void __launch_bounds__(32 * WPB, 2) pass1_kernel(
    const float* __restrict__ feats, const int* __restrict__ bidx,
    const float* __restrict__ w1,  const float* __restrict__ b1,
    const float* __restrict__ mw1, const float* __restrict__ mb1,
    const float* __restrict__ mw2, const float* __restrict__ mb2,
    float* __restrict__ mask_out, int n, int tiles_total, int tpw)
{
    __shared__ float sx[WPB][TP * XP];
    __shared__ int   sb[WPB][TP];

    const int lane = threadIdx.x & 31;
    const int wi   = threadIdx.x >> 5;
    const int tg   = lane & 3;
    const int grp  = lane >> 2;

    u32 Wh[4][4][2], Wl[4][4][2], Mh[4][4][2];
#pragma unroll
    for (int kb = 0; kb < 4; kb++)
#pragma unroll
        for (int nb = 0; nb < 4; nb++) {
            int r0 = kb * 8 + tg, col = nb * 8 + grp;
            split_tf(w1[r0 * C + col],       Wh[kb][nb][0], Wl[kb][nb][0]);
            split_tf(w1[(r0 + 4) * C + col], Wh[kb][nb][1], Wl[kb][nb][1]);
            Mh[kb][nb][0] = f2tf(mw1[r0 * C + col]);
            Mh[kb][nb][1] = f2tf(mw1[(r0 + 4) * C + col]);
        }
    float hb[8], mbv[8], mwv[8];
#pragma unroll
    for (int i = 0; i < 8; i++) {
        int ch = CH(i, tg);
        hb[i]  = b1[ch];
        mbv[i] = mb1[ch];
        mwv[i] = mw2[ch];
    }
    const float mb2v = mb2[0];

    float s[8], s2[8];
#pragma unroll
    for (int i = 0; i < 8; i++) { s[i] = 0.f; s2[i] = 0.f; }

    float pacc = 0.f;
    int   pcnt = 0, cur_b = -1;

    const int gwid = blockIdx.x * WPB + wi;
    int t0 = gwid * tpw;
    int t1 = t0 + tpw; if (t1 > tiles_total) t1 = tiles_total;

    float* SX = sx[wi];
    int*   SB = sb[wi];

    for (int tile = t0; tile < t1; tile++) {
        const int base = tile * TP;
        int valid = n - base; if (valid > TP) valid = TP;
        const int lim = valid * 8;
        const float4* src = (const float4*)(feats + (size_t)base * C);
#pragma unroll
        for (int j = 0; j < 8; j++) {
            int L = lane + 32 * j;
            float4 v = make_float4(0.f, 0.f, 0.f, 0.f);
            if (L < lim) v = src[L];
            *(float4*)&SX[(L >> 3) * XP + 4 * (L & 7)] = v;
        }
        if (lane < valid) SB[lane] = bidx[base + lane];
        __syncwarp();

        u32 ah[2][4][4], al[2][4][4];
#pragma unroll
        for (int m = 0; m < 2; m++)
#pragma unroll
            for (int kb = 0; kb < 4; kb++) {
                int r = m * 16 + grp;
                split_tf(SX[r * XP + kb * 8 + tg],           ah[m][kb][0], al[m][kb][0]);
                split_tf(SX[(r + 8) * XP + kb * 8 + tg],     ah[m][kb][1], al[m][kb][1]);
                split_tf(SX[r * XP + kb * 8 + tg + 4],       ah[m][kb][2], al[m][kb][2]);
                split_tf(SX[(r + 8) * XP + kb * 8 + tg + 4], ah[m][kb][3], al[m][kb][3]);
            }

        const bool full = (valid == TP);
        u32* hout = g_h + (size_t)tile * 512;

        // --- h GEMM + stats + fp16 spill ---
#pragma unroll
        for (int nb = 0; nb < 4; nb++) {
            float d[2][4];
#pragma unroll
            for (int m = 0; m < 2; m++) {
                d[m][0] = hb[2 * nb]; d[m][1] = hb[2 * nb + 1];
                d[m][2] = hb[2 * nb]; d[m][3] = hb[2 * nb + 1];
            }
#pragma unroll
            for (int kb = 0; kb < 4; kb++)
#pragma unroll
                for (int m = 0; m < 2; m++) {
                    MMA(d[m][0], d[m][1], d[m][2], d[m][3],
                        ah[m][kb][0], ah[m][kb][1], ah[m][kb][2], ah[m][kb][3],
                        Wl[kb][nb][0], Wl[kb][nb][1]);
                    MMA(d[m][0], d[m][1], d[m][2], d[m][3],
                        al[m][kb][0], al[m][kb][1], al[m][kb][2], al[m][kb][3],
                        Wh[kb][nb][0], Wh[kb][nb][1]);
                    MMA(d[m][0], d[m][1], d[m][2], d[m][3],
                        ah[m][kb][0], ah[m][kb][1], ah[m][kb][2], ah[m][kb][3],
                        Wh[kb][nb][0], Wh[kb][nb][1]);
                }
            if (full) {
#pragma unroll
                for (int m = 0; m < 2; m++) {
                    s[2 * nb]      += d[m][0] + d[m][2];
                    s2[2 * nb]      = fmaf(d[m][0], d[m][0], fmaf(d[m][2], d[m][2], s2[2 * nb]));
                    s[2 * nb + 1]  += d[m][1] + d[m][3];
                    s2[2 * nb + 1]  = fmaf(d[m][1], d[m][1], fmaf(d[m][3], d[m][3], s2[2 * nb + 1]));
                }
            } else {
#pragma unroll
                for (int m = 0; m < 2; m++) {
                    if (base + m * 16 + grp < n) {
                        s[2 * nb] += d[m][0];     s2[2 * nb]     = fmaf(d[m][0], d[m][0], s2[2 * nb]);
                        s[2 * nb + 1] += d[m][1]; s2[2 * nb + 1] = fmaf(d[m][1], d[m][1], s2[2 * nb + 1]);
                    }
                    if (base + m * 16 + grp + 8 < n) {
                        s[2 * nb] += d[m][2];     s2[2 * nb]     = fmaf(d[m][2], d[m][2], s2[2 * nb]);
                        s[2 * nb + 1] += d[m][3]; s2[2 * nb + 1] = fmaf(d[m][3], d[m][3], s2[2 * nb + 1]);
                    }
                }
            }
            // spill h as fp16 pairs; layout: ((m*2+rh)*4 + nb)*32 + lane
#pragma unroll
            for (int m = 0; m < 2; m++) {
                __half2 v0 = __floats2half2_rn(d[m][0], d[m][1]);
                __half2 v1 = __floats2half2_rn(d[m][2], d[m][3]);
                hout[((m * 2 + 0) * 4 + nb) * 32 + lane] = *(u32*)&v0;
                hout[((m * 2 + 1) * 4 + nb) * 32 + lane] = *(u32*)&v1;
            }
        }

        // --- mask GEMM (2-term) + projection ---
        float p[2][2] = {{0.f, 0.f}, {0.f, 0.f}};
#pragma unroll
        for (int nb = 0; nb < 4; nb++) {
            float d[2][4];
#pragma unroll
            for (int m = 0; m < 2; m++) {
                d[m][0] = mbv[2 * nb]; d[m][1] = mbv[2 * nb + 1];
                d[m][2] = mbv[2 * nb]; d[m][3] = mbv[2 * nb + 1];
            }
#pragma unroll
            for (int kb = 0; kb < 4; kb++)
#pragma unroll
                for (int m = 0; m < 2; m++) {
                    MMA(d[m][0], d[m][1], d[m][2], d[m][3],
                        al[m][kb][0], al[m][kb][1], al[m][kb][2], al[m][kb][3],
                        Mh[kb][nb][0], Mh[kb][nb][1]);
                    MMA(d[m][0], d[m][1], d[m][2], d[m][3],
                        ah[m][kb][0], ah[m][kb][1], ah[m][kb][2], ah[m][kb][3],
                        Mh[kb][nb][0], Mh[kb][nb][1]);
                }
#pragma unroll
            for (int m = 0; m < 2; m++) {
                p[m][0] = fmaf(fmaxf(d[m][0], 0.f), mwv[2 * nb],
                          fmaf(fmaxf(d[m][1], 0.f), mwv[2 * nb + 1], p[m][0]));
                p[m][1] = fmaf(fmaxf(d[m][2], 0.f), mwv[2 * nb],
                          fmaf(fmaxf(d[m][3], 0.f), mwv[2 * nb + 1], p[m][1]));
            }
        }
#pragma unroll
        for (int m = 0; m < 2; m++) {
            p[m][0] += __shfl_xor_sync(0xffffffffu, p[m][0], 1);
            p[m][0] += __shfl_xor_sync(0xffffffffu, p[m][0], 2);
            p[m][1] += __shfl_xor_sync(0xffffffffu, p[m][1], 1);
            p[m][1] += __shfl_xor_sync(0xffffffffu, p[m][1], 2);
        }
        if (tg == 0) {
#pragma unroll
            for (int m = 0; m < 2; m++) {
                int r = m * 16 + grp;
                if (r < valid)     mask_out[base + r]     = p[m][0] + mb2v;
                if (r + 8 < valid) mask_out[base + r + 8] = p[m][1] + mb2v;
            }
        }

        // --- pooled (lane = channel) ---
        if (full && SB[0] == SB[TP - 1]) {
            int b = SB[0];
            if (b != cur_b) {
                if (cur_b >= 0) {
                    atomicAdd(&g_pool[cur_b * C + lane], pacc);
                    if (lane == 0) atomicAdd(&g_cnt[cur_b], (float)pcnt);
                }
                cur_b = b; pacc = 0.f; pcnt = 0;
            }
            float a = 0.f;
#pragma unroll
            for (int pnt = 0; pnt < TP; pnt++) a += SX[pnt * XP + lane];
            pacc += a; pcnt += TP;
        } else {
            for (int pnt = 0; pnt < valid; pnt++) {
                int b = SB[pnt];
                if (b != cur_b) {
                    if (cur_b >= 0) {
                        atomicAdd(&g_pool[cur_b * C + lane], pacc);
                        if (lane == 0) atomicAdd(&g_cnt[cur_b], (float)pcnt);
                    }
                    cur_b = b; pacc = 0.f; pcnt = 0;
                }
                pacc += SX[pnt * XP + lane];
                pcnt++;
            }
        }
        __syncwarp();
    }

    if (cur_b >= 0) {
        atomicAdd(&g_pool[cur_b * C + lane], pacc);
        if (lane == 0) atomicAdd(&g_cnt[cur_b], (float)pcnt);
    }
#pragma unroll
    for (int i = 0; i < 8; i++) {
#pragma unroll
        for (int o = 4; o < 32; o <<= 1) {
            s[i]  += __shfl_xor_sync(0xffffffffu, s[i],  o);
            s2[i] += __shfl_xor_sync(0xffffffffu, s2[i], o);
        }
    }
    if (grp == 0) {
#pragma unroll
        for (int i = 0; i < 8; i++) {
            int ch = CH(i, tg);
            atomicAdd(&g_sumH[ch],  s[i]);
            atomicAdd(&g_sumH2[ch], s2[i]);
        }
    }
}

// ================= FINALIZE =================
__global__ void finalize_kernel(
    const float* __restrict__ gamma, const float* __restrict__ beta,
    const float* __restrict__ iou_w, const float* __restrict__ iou_b,
    float* __restrict__ out_pooled, float* __restrict__ out_iou,
    int n, int B)
{
    int t = threadIdx.x;
    float inv = 1.f / (float)n;
    float mu  = g_sumH[t] * inv;
    float var = g_sumH2[t] * inv - mu * mu;
    float sc  = gamma[t] * rsqrtf(var + 1e-4f);
    g_bns[t] = sc;
    g_bnt[t] = beta[t] - mu * sc;

    float iw = iou_w[t];
    for (int b = 0; b < B; b++) {
        float cnt = fmaxf(g_cnt[b], 1.f);
        float pm  = g_pool[b * C + t] / cnt;
        out_pooled[b * C + t] = pm;
        float v = pm * iw;
#pragma unroll
        for (int o = 16; o > 0; o >>= 1) v += __shfl_xor_sync(0xffffffffu, v, o);
        if (t == 0) out_iou[b] = v + iou_b[0];
    }
}

// ================= PASS 2 (streaming) =================
__global__ void __launch_bounds__(32 * WPB, 8) pass2_kernel(
    const float* __restrict__ w2, const float* __restrict__ ob2,
    float* __restrict__ off_out, int n, int tiles_total, int tpw)
{
    const int lane = threadIdx.x & 31;
    const int wi   = threadIdx.x >> 5;
    const int tg   = lane & 3;
    const int grp  = lane >> 2;

    float sv[8], tv[8], w2v0[8], w2v1[8], w2v2[8];
#pragma unroll
    for (int i = 0; i < 8; i++) {
        int ch = CH(i, tg);
        sv[i]   = g_bns[ch];
        tv[i]   = g_bnt[ch];
        w2v0[i] = w2[ch * 3 + 0];
        w2v1[i] = w2[ch * 3 + 1];
        w2v2[i] = w2[ch * 3 + 2];
    }
    const float c0 = ob2[0], c1 = ob2[1], c2 = ob2[2];

    const int gwid = blockIdx.x * WPB + wi;
    int t0 = gwid * tpw;
    int t1 = t0 + tpw; if (t1 > tiles_total) t1 = tiles_total;

    for (int tile = t0; tile < t1; tile++) {
        const int base = tile * TP;
        int valid = n - base; if (valid > TP) valid = TP;
        const u32* hp = g_h + (size_t)tile * 512;

        float o0[2][2], o1[2][2], o2[2][2];
#pragma unroll
        for (int m = 0; m < 2; m++)
#pragma unroll
            for (int r = 0; r < 2; r++) { o0[m][r] = 0.f; o1[m][r] = 0.f; o2[m][r] = 0.f; }

#pragma unroll
        for (int m = 0; m < 2; m++)
#pragma unroll
            for (int nb = 0; nb < 4; nb++) {
                u32 v0 = hp[((m * 2 + 0) * 4 + nb) * 32 + lane];
                u32 v1 = hp[((m * 2 + 1) * 4 + nb) * 32 + lane];
                float2 a = __half22float2(*(__half2*)&v0);
                float2 b = __half22float2(*(__half2*)&v1);
                int i0 = 2 * nb, i1 = 2 * nb + 1;
                float e0 = fmaxf(fmaf(a.x, sv[i0], tv[i0]), 0.f);
                float e1 = fmaxf(fmaf(a.y, sv[i1], tv[i1]), 0.f);
                float e2 = fmaxf(fmaf(b.x, sv[i0], tv[i0]), 0.f);
                float e3 = fmaxf(fmaf(b.y, sv[i1], tv[i1]), 0.f);
                o0[m][0] = fmaf(e0, w2v0[i0], fmaf(e1, w2v0[i1], o0[m][0]));
                o1[m][0] = fmaf(e0, w2v1[i0], fmaf(e1, w2v1[i1], o1[m][0]));
                o2[m][0] = fmaf(e0, w2v2[i0], fmaf(e1, w2v2[i1], o2[m][0]));
                o0[m][1] = fmaf(e2, w2v0[i0], fmaf(e3, w2v0[i1], o0[m][1]));
                o1[m][1] = fmaf(e2, w2v1[i0], fmaf(e3, w2v1[i1], o1[m][1]));
                o2[m][1] = fmaf(e2, w2v2[i0], fmaf(e3, w2v2[i1], o2[m][1]));
            }
#pragma unroll
        for (int m = 0; m < 2; m++)
#pragma unroll
            for (int r = 0; r < 2; r++) {
#pragma unroll
                for (int o = 1; o <= 2; o <<= 1) {
                    o0[m][r] += __shfl_xor_sync(0xffffffffu, o0[m][r], o);
                    o1[m][r] += __shfl_xor_sync(0xffffffffu, o1[m][r], o);
                    o2[m][r] += __shfl_xor_sync(0xffffffffu, o2[m][r], o);
                }
            }
        if (tg == 0) {
#pragma unroll
            for (int m = 0; m < 2; m++)
#pragma unroll
                for (int r = 0; r < 2; r++) {
                    int row = m * 16 + grp + r * 8;
                    if (row < valid) {
                        size_t o = (size_t)(base + row) * 3;
                        off_out[o + 0] = o0[m][r] + c0;
                        off_out[o + 1] = o1[m][r] + c1;
                        off_out[o + 2] = o2[m][r] + c2;
                    }
                }
        }
    }
}

// ================= LAUNCH =================
extern "C" void kernel_launch(void* const* d_in, const int* in_sizes, int n_in,
                              void* d_out, int out_size) {
    const float* feats = (const float*)d_in[0];
    const int*   bidx  = (const int*)  d_in[1];
    const float* w1    = (const float*)d_in[2];
    const float* b1    = (const float*)d_in[3];
    const float* gamma = (const float*)d_in[4];
    const float* beta  = (const float*)d_in[5];
    const float* w2    = (const float*)d_in[6];
    const float* ob2   = (const float*)d_in[7];
    const float* mw1   = (const float*)d_in[8];
    const float* mb1   = (const float*)d_in[9];
    const float* mw2   = (const float*)d_in[10];
    const float* mb2   = (const float*)d_in[11];
    const float* iw    = (const float*)d_in[12];
    const float* ib    = (const float*)d_in[13];

    int n = in_sizes[1];
    int B = (out_size - 4 * n) / 33;
    if (B < 1) B = 1;
    if (B > 64) B = 64;

    float* out        = (float*)d_out;
    float* out_off    = out;
    float* out_mask   = out + (size_t)3 * n;
    float* out_pooled = out + (size_t)4 * n;
    float* out_iou    = out_pooled + (size_t)B * C;

    int tiles  = (n + TP - 1) / TP;
    if (tiles > HCAP_TILES) tiles = HCAP_TILES;   // capacity guard (N=2M fits)
    int blocks = 608;
    int warps  = blocks * WPB;
    int tpw    = (tiles + warps - 1) / warps;

    zero_kernel<<<1, 1024>>>(B);
    pass1_kernel<<<blocks, 32 * WPB>>>(feats, bidx, w1, b1, mw1, mb1, mw2, mb2,
                                       out_mask, n, tiles, tpw);
    finalize_kernel<<<1, 32>>>(gamma, beta, iw, ib, out_pooled, out_iou, n, B);
    pass2_kernel<<<blocks, 32 * WPB>>>(w2, ob2, out_off, n, tiles, tpw);
}

// round 7
// speedup vs baseline: 1.3417x; 1.3417x over previous
#include <cuda_runtime.h>

// InstHead fused. R7: back to R5 recompute structure (no spill); all GEMMs use
// 2-term TF32 split (full-A x tf32-W): pass1 128 MMAs/tile, pass2 64 MMAs/tile.

#define C 32
#define WPB 4
typedef unsigned int u32;

__device__ __forceinline__ u32 f2tf(float x) {
    u32 r; asm("cvt.rna.tf32.f32 %0, %1;" : "=r"(r) : "f"(x)); return r;
}
__device__ __forceinline__ void split_tf(float x, u32& hi, u32& lo) {
    hi = f2tf(x);
    lo = f2tf(x - __uint_as_float(hi));
}

#define MMA(d0,d1,d2,d3,a0,a1,a2,a3,b0,b1) \
    asm("mma.sync.aligned.m16n8k8.row.col.f32.tf32.tf32.f32 " \
        "{%0,%1,%2,%3}, {%4,%5,%6,%7}, {%8,%9}, {%0,%1,%2,%3};" \
        : "+f"(d0), "+f"(d1), "+f"(d2), "+f"(d3) \
        : "r"(a0), "r"(a1), "r"(a2), "r"(a3), "r"(b0), "r"(b1))

// ---- scratch ----
__device__ float g_pool[64 * C];
__device__ float g_cnt[64];
__device__ float g_sumH[C];
__device__ float g_sumH2[C];
__device__ float g_w1f[C * C];
__device__ float g_b1f[C];

__global__ void zero_kernel(int B) {
    int t = threadIdx.x;
    for (int i = t; i < B * C; i += blockDim.x) g_pool[i] = 0.f;
    if (t < B) g_cnt[t] = 0.f;
    if (t < C) { g_sumH[t] = 0.f; g_sumH2[t] = 0.f; }
}

#define XP 36
#define TP 32
#define CH(i, tg) (((i) >> 1) * 8 + 2 * (tg) + ((i) & 1))

// ================= PASS 1 =================
__global__ void __launch_bounds__(32 * WPB, 2) pass1_kernel(
    const float* __restrict__ feats, const int* __restrict__ bidx,
    const float* __restrict__ w1,  const float* __restrict__ b1,
    const float* __restrict__ mw1, const float* __restrict__ mb1,
    const float* __restrict__ mw2, const float* __restrict__ mb2,
    float* __restrict__ mask_out, int n, int tiles_total, int tpw)
{
    __shared__ float sx[WPB][TP * XP];
    __shared__ int   sb[WPB][TP];

    const int lane = threadIdx.x & 31;
    const int wi   = threadIdx.x >> 5;
    const int tg   = lane & 3;
    const int grp  = lane >> 2;

    // 2-term: only hi-precision weights needed
    u32 Wh[4][4][2], Mh[4][4][2];
#pragma unroll
    for (int kb = 0; kb < 4; kb++)
#pragma unroll
        for (int nb = 0; nb < 4; nb++) {
            int r0 = kb * 8 + tg, col = nb * 8 + grp;
            Wh[kb][nb][0] = f2tf(w1[r0 * C + col]);
            Wh[kb][nb][1] = f2tf(w1[(r0 + 4) * C + col]);
            Mh[kb][nb][0] = f2tf(mw1[r0 * C + col]);
            Mh[kb][nb][1] = f2tf(mw1[(r0 + 4) * C + col]);
        }
    float hb[8], mbv[8], mwv[8];
#pragma unroll
    for (int i = 0; i < 8; i++) {
        int ch = CH(i, tg);
        hb[i]  = b1[ch];
        mbv[i] = mb1[ch];
        mwv[i] = mw2[ch];
    }
    const float mb2v = mb2[0];

    float s[8], s2[8];
#pragma unroll
    for (int i = 0; i < 8; i++) { s[i] = 0.f; s2[i] = 0.f; }

    float pacc = 0.f;
    int   pcnt = 0, cur_b = -1;

    const int gwid = blockIdx.x * WPB + wi;
    int t0 = gwid * tpw;
    int t1 = t0 + tpw; if (t1 > tiles_total) t1 = tiles_total;

    float* SX = sx[wi];
    int*   SB = sb[wi];

    for (int tile = t0; tile < t1; tile++) {
        const int base = tile * TP;
        int valid = n - base; if (valid > TP) valid = TP;
        const int lim = valid * 8;
        const float4* src = (const float4*)(feats + (size_t)base * C);
#pragma unroll
        for (int j = 0; j < 8; j++) {
            int L = lane + 32 * j;
            float4 v = make_float4(0.f, 0.f, 0.f, 0.f);
            if (L < lim) v = src[L];
            *(float4*)&SX[(L >> 3) * XP + 4 * (L & 7)] = v;
        }
        if (lane < valid) SB[lane] = bidx[base + lane];
        __syncwarp();

        u32 ah[2][4][4], al[2][4][4];
#pragma unroll
        for (int m = 0; m < 2; m++)
#pragma unroll
            for (int kb = 0; kb < 4; kb++) {
                int r = m * 16 + grp;
                split_tf(SX[r * XP + kb * 8 + tg],           ah[m][kb][0], al[m][kb][0]);
                split_tf(SX[(r + 8) * XP + kb * 8 + tg],     ah[m][kb][1], al[m][kb][1]);
                split_tf(SX[r * XP + kb * 8 + tg + 4],       ah[m][kb][2], al[m][kb][2]);
                split_tf(SX[(r + 8) * XP + kb * 8 + tg + 4], ah[m][kb][3], al[m][kb][3]);
            }

        const bool full = (valid == TP);

        // --- h GEMM (2-term) + stats ---
#pragma unroll
        for (int nb = 0; nb < 4; nb++) {
            float d[2][4];
#pragma unroll
            for (int m = 0; m < 2; m++) {
                d[m][0] = hb[2 * nb]; d[m][1] = hb[2 * nb + 1];
                d[m][2] = hb[2 * nb]; d[m][3] = hb[2 * nb + 1];
            }
#pragma unroll
            for (int kb = 0; kb < 4; kb++)
#pragma unroll
                for (int m = 0; m < 2; m++) {
                    MMA(d[m][0], d[m][1], d[m][2], d[m][3],
                        al[m][kb][0], al[m][kb][1], al[m][kb][2], al[m][kb][3],
                        Wh[kb][nb][0], Wh[kb][nb][1]);
                    MMA(d[m][0], d[m][1], d[m][2], d[m][3],
                        ah[m][kb][0], ah[m][kb][1], ah[m][kb][2], ah[m][kb][3],
                        Wh[kb][nb][0], Wh[kb][nb][1]);
                }
            if (full) {
#pragma unroll
                for (int m = 0; m < 2; m++) {
                    s[2 * nb]      += d[m][0] + d[m][2];
                    s2[2 * nb]      = fmaf(d[m][0], d[m][0], fmaf(d[m][2], d[m][2], s2[2 * nb]));
                    s[2 * nb + 1]  += d[m][1] + d[m][3];
                    s2[2 * nb + 1]  = fmaf(d[m][1], d[m][1], fmaf(d[m][3], d[m][3], s2[2 * nb + 1]));
                }
            } else {
#pragma unroll
                for (int m = 0; m < 2; m++) {
                    if (base + m * 16 + grp < n) {
                        s[2 * nb] += d[m][0];     s2[2 * nb]     = fmaf(d[m][0], d[m][0], s2[2 * nb]);
                        s[2 * nb + 1] += d[m][1]; s2[2 * nb + 1] = fmaf(d[m][1], d[m][1], s2[2 * nb + 1]);
                    }
                    if (base + m * 16 + grp + 8 < n) {
                        s[2 * nb] += d[m][2];     s2[2 * nb]     = fmaf(d[m][2], d[m][2], s2[2 * nb]);
                        s[2 * nb + 1] += d[m][3]; s2[2 * nb + 1] = fmaf(d[m][3], d[m][3], s2[2 * nb + 1]);
                    }
                }
            }
        }

        // --- mask GEMM (2-term) + projection ---
        float p[2][2] = {{0.f, 0.f}, {0.f, 0.f}};
#pragma unroll
        for (int nb = 0; nb < 4; nb++) {
            float d[2][4];
#pragma unroll
            for (int m = 0; m < 2; m++) {
                d[m][0] = mbv[2 * nb]; d[m][1] = mbv[2 * nb + 1];
                d[m][2] = mbv[2 * nb]; d[m][3] = mbv[2 * nb + 1];
            }
#pragma unroll
            for (int kb = 0; kb < 4; kb++)
#pragma unroll
                for (int m = 0; m < 2; m++) {
                    MMA(d[m][0], d[m][1], d[m][2], d[m][3],
                        al[m][kb][0], al[m][kb][1], al[m][kb][2], al[m][kb][3],
                        Mh[kb][nb][0], Mh[kb][nb][1]);
                    MMA(d[m][0], d[m][1], d[m][2], d[m][3],
                        ah[m][kb][0], ah[m][kb][1], ah[m][kb][2], ah[m][kb][3],
                        Mh[kb][nb][0], Mh[kb][nb][1]);
                }
#pragma unroll
            for (int m = 0; m < 2; m++) {
                p[m][0] = fmaf(fmaxf(d[m][0], 0.f), mwv[2 * nb],
                          fmaf(fmaxf(d[m][1], 0.f), mwv[2 * nb + 1], p[m][0]));
                p[m][1] = fmaf(fmaxf(d[m][2], 0.f), mwv[2 * nb],
                          fmaf(fmaxf(d[m][3], 0.f), mwv[2 * nb + 1], p[m][1]));
            }
        }
#pragma unroll
        for (int m = 0; m < 2; m++) {
            p[m][0] += __shfl_xor_sync(0xffffffffu, p[m][0], 1);
            p[m][0] += __shfl_xor_sync(0xffffffffu, p[m][0], 2);
            p[m][1] += __shfl_xor_sync(0xffffffffu, p[m][1], 1);
            p[m][1] += __shfl_xor_sync(0xffffffffu, p[m][1], 2);
        }
        if (tg == 0) {
#pragma unroll
            for (int m = 0; m < 2; m++) {
                int r = m * 16 + grp;
                if (r < valid)     mask_out[base + r]     = p[m][0] + mb2v;
                if (r + 8 < valid) mask_out[base + r + 8] = p[m][1] + mb2v;
            }
        }

        // --- pooled (lane = channel) ---
        if (full && SB[0] == SB[TP - 1]) {
            int b = SB[0];
            if (b != cur_b) {
                if (cur_b >= 0) {
                    atomicAdd(&g_pool[cur_b * C + lane], pacc);
                    if (lane == 0) atomicAdd(&g_cnt[cur_b], (float)pcnt);
                }
                cur_b = b; pacc = 0.f; pcnt = 0;
            }
            float a = 0.f;
#pragma unroll
            for (int pnt = 0; pnt < TP; pnt++) a += SX[pnt * XP + lane];
            pacc += a; pcnt += TP;
        } else {
            for (int pnt = 0; pnt < valid; pnt++) {
                int b = SB[pnt];
                if (b != cur_b) {
                    if (cur_b >= 0) {
                        atomicAdd(&g_pool[cur_b * C + lane], pacc);
                        if (lane == 0) atomicAdd(&g_cnt[cur_b], (float)pcnt);
                    }
                    cur_b = b; pacc = 0.f; pcnt = 0;
                }
                pacc += SX[pnt * XP + lane];
                pcnt++;
            }
        }
        __syncwarp();
    }

    if (cur_b >= 0) {
        atomicAdd(&g_pool[cur_b * C + lane], pacc);
        if (lane == 0) atomicAdd(&g_cnt[cur_b], (float)pcnt);
    }
#pragma unroll
    for (int i = 0; i < 8; i++) {
#pragma unroll
        for (int o = 4; o < 32; o <<= 1) {
            s[i]  += __shfl_xor_sync(0xffffffffu, s[i],  o);
            s2[i] += __shfl_xor_sync(0xffffffffu, s2[i], o);
        }
    }
    if (grp == 0) {
#pragma unroll
        for (int i = 0; i < 8; i++) {
            int ch = CH(i, tg);
            atomicAdd(&g_sumH[ch],  s[i]);
            atomicAdd(&g_sumH2[ch], s2[i]);
        }
    }
}

// ================= FINALIZE =================
__global__ void finalize_kernel(
    const float* __restrict__ w1, const float* __restrict__ b1,
    const float* __restrict__ gamma, const float* __restrict__ beta,
    const float* __restrict__ iou_w, const float* __restrict__ iou_b,
    float* __restrict__ out_pooled, float* __restrict__ out_iou,
    int n, int B)
{
    int t = threadIdx.x;
    float inv = 1.f / (float)n;
    float mu  = g_sumH[t] * inv;
    float var = g_sumH2[t] * inv - mu * mu;
    float sc  = gamma[t] * rsqrtf(var + 1e-4f);
    g_b1f[t] = beta[t] + (b1[t] - mu) * sc;
#pragma unroll
    for (int k = 0; k < C; k++) g_w1f[k * C + t] = w1[k * C + t] * sc;

    float iw = iou_w[t];
    for (int b = 0; b < B; b++) {
        float cnt = fmaxf(g_cnt[b], 1.f);
        float pm  = g_pool[b * C + t] / cnt;
        out_pooled[b * C + t] = pm;
        float v = pm * iw;
#pragma unroll
        for (int o = 16; o > 0; o >>= 1) v += __shfl_xor_sync(0xffffffffu, v, o);
        if (t == 0) out_iou[b] = v + iou_b[0];
    }
}

// ================= PASS 2 =================
__global__ void __launch_bounds__(32 * WPB, 3) pass2_kernel(
    const float* __restrict__ feats,
    const float* __restrict__ w2, const float* __restrict__ ob2,
    float* __restrict__ off_out, int n, int tiles_total, int tpw)
{
    __shared__ float sx[WPB][TP * XP];

    const int lane = threadIdx.x & 31;
    const int wi   = threadIdx.x >> 5;
    const int tg   = lane & 3;
    const int grp  = lane >> 2;

    u32 Wh[4][4][2];
#pragma unroll
    for (int kb = 0; kb < 4; kb++)
#pragma unroll
        for (int nb = 0; nb < 4; nb++) {
            int r0 = kb * 8 + tg, col = nb * 8 + grp;
            Wh[kb][nb][0] = f2tf(g_w1f[r0 * C + col]);
            Wh[kb][nb][1] = f2tf(g_w1f[(r0 + 4) * C + col]);
        }
    float fb[8], w2v0[8], w2v1[8], w2v2[8];
#pragma unroll
    for (int i = 0; i < 8; i++) {
        int ch = CH(i, tg);
        fb[i]   = g_b1f[ch];
        w2v0[i] = w2[ch * 3 + 0];
        w2v1[i] = w2[ch * 3 + 1];
        w2v2[i] = w2[ch * 3 + 2];
    }
    const float c0 = ob2[0], c1 = ob2[1], c2 = ob2[2];

    const int gwid = blockIdx.x * WPB + wi;
    int t0 = gwid * tpw;
    int t1 = t0 + tpw; if (t1 > tiles_total) t1 = tiles_total;

    float* SX = sx[wi];

    for (int tile = t0; tile < t1; tile++) {
        const int base = tile * TP;
        int valid = n - base; if (valid > TP) valid = TP;
        const int lim = valid * 8;
        const float4* src = (const float4*)(feats + (size_t)base * C);
#pragma unroll
        for (int j = 0; j < 8; j++) {
            int L = lane + 32 * j;
            float4 v = make_float4(0.f, 0.f, 0.f, 0.f);
            if (L < lim) v = src[L];
            *(float4*)&SX[(L >> 3) * XP + 4 * (L & 7)] = v;
        }
        __syncwarp();

        u32 ah[2][4][4], al[2][4][4];
#pragma unroll
        for (int m = 0; m < 2; m++)
#pragma unroll
            for (int kb = 0; kb < 4; kb++) {
                int r = m * 16 + grp;
                split_tf(SX[r * XP + kb * 8 + tg],           ah[m][kb][0], al[m][kb][0]);
                split_tf(SX[(r + 8) * XP + kb * 8 + tg],     ah[m][kb][1], al[m][kb][1]);
                split_tf(SX[r * XP + kb * 8 + tg + 4],       ah[m][kb][2], al[m][kb][2]);
                split_tf(SX[(r + 8) * XP + kb * 8 + tg + 4], ah[m][kb][3], al[m][kb][3]);
            }

        float o0[2][2], o1[2][2], o2[2][2];
#pragma unroll
        for (int m = 0; m < 2; m++)
#pragma unroll
            for (int r = 0; r < 2; r++) { o0[m][r] = 0.f; o1[m][r] = 0.f; o2[m][r] = 0.f; }

#pragma unroll
        for (int nb = 0; nb < 4; nb++) {
            float d[2][4];
#pragma unroll
            for (int m = 0; m < 2; m++) {
                d[m][0] = fb[2 * nb]; d[m][1] = fb[2 * nb + 1];
                d[m][2] = fb[2 * nb]; d[m][3] = fb[2 * nb + 1];
            }
#pragma unroll
            for (int kb = 0; kb < 4; kb++)
#pragma unroll
                for (int m = 0; m < 2; m++) {
                    MMA(d[m][0], d[m][1], d[m][2], d[m][3],
                        al[m][kb][0], al[m][kb][1], al[m][kb][2], al[m][kb][3],
                        Wh[kb][nb][0], Wh[kb][nb][1]);
                    MMA(d[m][0], d[m][1], d[m][2], d[m][3],
                        ah[m][kb][0], ah[m][kb][1], ah[m][kb][2], ah[m][kb][3],
                        Wh[kb][nb][0], Wh[kb][nb][1]);
                }
#pragma unroll
            for (int m = 0; m < 2; m++) {
                float e0 = fmaxf(d[m][0], 0.f), e1 = fmaxf(d[m][1], 0.f);
                float e2 = fmaxf(d[m][2], 0.f), e3 = fmaxf(d[m][3], 0.f);
                o0[m][0] = fmaf(e0, w2v0[2 * nb], fmaf(e1, w2v0[2 * nb + 1], o0[m][0]));
                o1[m][0] = fmaf(e0, w2v1[2 * nb], fmaf(e1, w2v1[2 * nb + 1], o1[m][0]));
                o2[m][0] = fmaf(e0, w2v2[2 * nb], fmaf(e1, w2v2[2 * nb + 1], o2[m][0]));
                o0[m][1] = fmaf(e2, w2v0[2 * nb], fmaf(e3, w2v0[2 * nb + 1], o0[m][1]));
                o1[m][1] = fmaf(e2, w2v1[2 * nb], fmaf(e3, w2v1[2 * nb + 1], o1[m][1]));
                o2[m][1] = fmaf(e2, w2v2[2 * nb], fmaf(e3, w2v2[2 * nb + 1], o2[m][1]));
            }
        }
#pragma unroll
        for (int m = 0; m < 2; m++)
#pragma unroll
            for (int r = 0; r < 2; r++) {
#pragma unroll
                for (int o = 1; o <= 2; o <<= 1) {
                    o0[m][r] += __shfl_xor_sync(0xffffffffu, o0[m][r], o);
                    o1[m][r] += __shfl_xor_sync(0xffffffffu, o1[m][r], o);
                    o2[m][r] += __shfl_xor_sync(0xffffffffu, o2[m][r], o);
                }
            }
        if (tg == 0) {
#pragma unroll
            for (int m = 0; m < 2; m++) {
#pragma unroll
                for (int r = 0; r < 2; r++) {
                    int row = m * 16 + grp + r * 8;
                    if (row < valid) {
                        size_t o = (size_t)(base + row) * 3;
                        off_out[o + 0] = o0[m][r] + c0;
                        off_out[o + 1] = o1[m][r] + c1;
                        off_out[o + 2] = o2[m][r] + c2;
                    }
                }
            }
        }
        __syncwarp();
    }
}

// ================= LAUNCH =================
extern "C" void kernel_launch(void* const* d_in, const int* in_sizes, int n_in,
                              void* d_out, int out_size) {
    const float* feats = (const float*)d_in[0];
    const int*   bidx  = (const int*)  d_in[1];
    const float* w1    = (const float*)d_in[2];
    const float* b1    = (const float*)d_in[3];
    const float* gamma = (const float*)d_in[4];
    const float* beta  = (const float*)d_in[5];
    const float* w2    = (const float*)d_in[6];
    const float* ob2   = (const float*)d_in[7];
    const float* mw1   = (const float*)d_in[8];
    const float* mb1   = (const float*)d_in[9];
    const float* mw2   = (const float*)d_in[10];
    const float* mb2   = (const float*)d_in[11];
    const float* iw    = (const float*)d_in[12];
    const float* ib    = (const float*)d_in[13];

    int n = in_sizes[1];
    int B = (out_size - 4 * n) / 33;
    if (B < 1) B = 1;
    if (B > 64) B = 64;

    float* out        = (float*)d_out;
    float* out_off    = out;
    float* out_mask   = out + (size_t)3 * n;
    float* out_pooled = out + (size_t)4 * n;
    float* out_iou    = out_pooled + (size_t)B * C;

    int tiles  = (n + TP - 1) / TP;
    int blocks = 608;
    int warps  = blocks * WPB;
    int tpw    = (tiles + warps - 1) / warps;

    zero_kernel<<<1, 1024>>>(B);
    pass1_kernel<<<blocks, 32 * WPB>>>(feats, bidx, w1, b1, mw1, mb1, mw2, mb2,
                                       out_mask, n, tiles, tpw);
    finalize_kernel<<<1, 32>>>(w1, b1, gamma, beta, iw, ib,
                               out_pooled, out_iou, n, B);
    pass2_kernel<<<blocks, 32 * WPB>>>(feats, w2, ob2, out_off, n, tiles, tpw);
}

// round 8
// speedup vs baseline: 1.7046x; 1.2704x over previous
#include <cuda_runtime.h>
#include <cuda_fp16.h>

// InstHead fused. R8: fp16 m16n8k16 MMAs with 2-term A split (A_hi+A_lo, W fp16).
// pass1: h GEMM (stats) + mask GEMM + pooled. pass2: BN-folded GEMM -> offsets.

#define C 32
#define WPB 4
typedef unsigned int u32;

__device__ __forceinline__ u32 packh2(float x, float y) {
    __half2 h = __floats2half2_rn(x, y);
    return *(u32*)&h;
}
__device__ __forceinline__ void split_h2(float x, float y, u32& hi, u32& lo) {
    __half2 h = __floats2half2_rn(x, y);
    float2 b = __half22float2(h);
    __half2 l = __floats2half2_rn(x - b.x, y - b.y);
    hi = *(u32*)&h;
    lo = *(u32*)&l;
}

#define MMA16(d0,d1,d2,d3,a0,a1,a2,a3,b0,b1) \
    asm("mma.sync.aligned.m16n8k16.row.col.f32.f16.f16.f32 " \
        "{%0,%1,%2,%3}, {%4,%5,%6,%7}, {%8,%9}, {%0,%1,%2,%3};" \
        : "+f"(d0), "+f"(d1), "+f"(d2), "+f"(d3) \
        : "r"(a0), "r"(a1), "r"(a2), "r"(a3), "r"(b0), "r"(b1))

// ---- scratch ----
__device__ float g_pool[64 * C];
__device__ float g_cnt[64];
__device__ float g_sumH[C];
__device__ float g_sumH2[C];
__device__ float g_w1f[C * C];
__device__ float g_b1f[C];

__global__ void zero_kernel(int B) {
    int t = threadIdx.x;
    for (int i = t; i < B * C; i += blockDim.x) g_pool[i] = 0.f;
    if (t < B) g_cnt[t] = 0.f;
    if (t < C) { g_sumH[t] = 0.f; g_sumH2[t] = 0.f; }
}

#define XP 36
#define TP 32
#define CH(i, tg) (((i) >> 1) * 8 + 2 * (tg) + ((i) & 1))

// load A fragments (hi/lo) for rows m*16+grp(+8), k-chunk kc*16
__device__ __forceinline__ void load_afrag(
    const float* SX, int m, int kc, int grp, int tg, u32* ah, u32* al)
{
    int r = m * 16 + grp;
    const float* p0 = &SX[r * XP + kc * 16 + 2 * tg];
    const float* p1 = &SX[(r + 8) * XP + kc * 16 + 2 * tg];
    float2 v0 = *(const float2*)p0;        // a0: row r,   k 2tg..
    float2 v1 = *(const float2*)p1;        // a1: row r+8
    float2 v2 = *(const float2*)(p0 + 8);  // a2: row r,   k 2tg+8
    float2 v3 = *(const float2*)(p1 + 8);  // a3: row r+8
    split_h2(v0.x, v0.y, ah[0], al[0]);
    split_h2(v1.x, v1.y, ah[1], al[1]);
    split_h2(v2.x, v2.y, ah[2], al[2]);
    split_h2(v3.x, v3.y, ah[3], al[3]);
}

// ================= PASS 1 =================
__global__ void __launch_bounds__(32 * WPB, 3) pass1_kernel(
    const float* __restrict__ feats, const int* __restrict__ bidx,
    const float* __restrict__ w1,  const float* __restrict__ b1,
    const float* __restrict__ mw1, const float* __restrict__ mb1,
    const float* __restrict__ mw2, const float* __restrict__ mb2,
    float* __restrict__ mask_out, int n, int tiles_total, int tpw)
{
    __shared__ float sx[WPB][TP * XP];
    __shared__ int   sb[WPB][TP];

    const int lane = threadIdx.x & 31;
    const int wi   = threadIdx.x >> 5;
    const int tg   = lane & 3;
    const int grp  = lane >> 2;

    // fp16 weight fragments: [kc][nb][2]
    u32 Wf[2][4][2], Mf[2][4][2];
#pragma unroll
    for (int kc = 0; kc < 2; kc++)
#pragma unroll
        for (int nb = 0; nb < 4; nb++) {
            int col = nb * 8 + grp;
            int k0 = kc * 16 + 2 * tg;
            Wf[kc][nb][0] = packh2(w1[k0 * C + col],       w1[(k0 + 1) * C + col]);
            Wf[kc][nb][1] = packh2(w1[(k0 + 8) * C + col], w1[(k0 + 9) * C + col]);
            Mf[kc][nb][0] = packh2(mw1[k0 * C + col],       mw1[(k0 + 1) * C + col]);
            Mf[kc][nb][1] = packh2(mw1[(k0 + 8) * C + col], mw1[(k0 + 9) * C + col]);
        }
    float hb[8], mbv[8], mwv[8];
#pragma unroll
    for (int i = 0; i < 8; i++) {
        int ch = CH(i, tg);
        hb[i]  = b1[ch];
        mbv[i] = mb1[ch];
        mwv[i] = mw2[ch];
    }
    const float mb2v = mb2[0];

    float s[8], s2[8];
#pragma unroll
    for (int i = 0; i < 8; i++) { s[i] = 0.f; s2[i] = 0.f; }

    float pacc = 0.f;
    int   pcnt = 0, cur_b = -1;

    const int gwid = blockIdx.x * WPB + wi;
    int t0 = gwid * tpw;
    int t1 = t0 + tpw; if (t1 > tiles_total) t1 = tiles_total;

    float* SX = sx[wi];
    int*   SB = sb[wi];

    for (int tile = t0; tile < t1; tile++) {
        const int base = tile * TP;
        int valid = n - base; if (valid > TP) valid = TP;
        const int lim = valid * 8;
        const float4* src = (const float4*)(feats + (size_t)base * C);
#pragma unroll
        for (int j = 0; j < 8; j++) {
            int L = lane + 32 * j;
            float4 v = make_float4(0.f, 0.f, 0.f, 0.f);
            if (L < lim) v = src[L];
            *(float4*)&SX[(L >> 3) * XP + 4 * (L & 7)] = v;
        }
        if (lane < valid) SB[lane] = bidx[base + lane];
        __syncwarp();

        u32 ah[2][2][4], al[2][2][4];   // [m][kc][4]
#pragma unroll
        for (int m = 0; m < 2; m++)
#pragma unroll
            for (int kc = 0; kc < 2; kc++)
                load_afrag(SX, m, kc, grp, tg, ah[m][kc], al[m][kc]);

        const bool full = (valid == TP);

        // --- h GEMM + stats ---
#pragma unroll
        for (int nb = 0; nb < 4; nb++) {
            float d[2][4];
#pragma unroll
            for (int m = 0; m < 2; m++) {
                d[m][0] = hb[2 * nb]; d[m][1] = hb[2 * nb + 1];
                d[m][2] = hb[2 * nb]; d[m][3] = hb[2 * nb + 1];
            }
#pragma unroll
            for (int kc = 0; kc < 2; kc++)
#pragma unroll
                for (int m = 0; m < 2; m++) {
                    MMA16(d[m][0], d[m][1], d[m][2], d[m][3],
                          al[m][kc][0], al[m][kc][1], al[m][kc][2], al[m][kc][3],
                          Wf[kc][nb][0], Wf[kc][nb][1]);
                    MMA16(d[m][0], d[m][1], d[m][2], d[m][3],
                          ah[m][kc][0], ah[m][kc][1], ah[m][kc][2], ah[m][kc][3],
                          Wf[kc][nb][0], Wf[kc][nb][1]);
                }
            if (full) {
#pragma unroll
                for (int m = 0; m < 2; m++) {
                    s[2 * nb]      += d[m][0] + d[m][2];
                    s2[2 * nb]      = fmaf(d[m][0], d[m][0], fmaf(d[m][2], d[m][2], s2[2 * nb]));
                    s[2 * nb + 1]  += d[m][1] + d[m][3];
                    s2[2 * nb + 1]  = fmaf(d[m][1], d[m][1], fmaf(d[m][3], d[m][3], s2[2 * nb + 1]));
                }
            } else {
#pragma unroll
                for (int m = 0; m < 2; m++) {
                    if (base + m * 16 + grp < n) {
                        s[2 * nb] += d[m][0];     s2[2 * nb]     = fmaf(d[m][0], d[m][0], s2[2 * nb]);
                        s[2 * nb + 1] += d[m][1]; s2[2 * nb + 1] = fmaf(d[m][1], d[m][1], s2[2 * nb + 1]);
                    }
                    if (base + m * 16 + grp + 8 < n) {
                        s[2 * nb] += d[m][2];     s2[2 * nb]     = fmaf(d[m][2], d[m][2], s2[2 * nb]);
                        s[2 * nb + 1] += d[m][3]; s2[2 * nb + 1] = fmaf(d[m][3], d[m][3], s2[2 * nb + 1]);
                    }
                }
            }
        }

        // --- mask GEMM + projection ---
        float p[2][2] = {{0.f, 0.f}, {0.f, 0.f}};
#pragma unroll
        for (int nb = 0; nb < 4; nb++) {
            float d[2][4];
#pragma unroll
            for (int m = 0; m < 2; m++) {
                d[m][0] = mbv[2 * nb]; d[m][1] = mbv[2 * nb + 1];
                d[m][2] = mbv[2 * nb]; d[m][3] = mbv[2 * nb + 1];
            }
#pragma unroll
            for (int kc = 0; kc < 2; kc++)
#pragma unroll
                for (int m = 0; m < 2; m++) {
                    MMA16(d[m][0], d[m][1], d[m][2], d[m][3],
                          al[m][kc][0], al[m][kc][1], al[m][kc][2], al[m][kc][3],
                          Mf[kc][nb][0], Mf[kc][nb][1]);
                    MMA16(d[m][0], d[m][1], d[m][2], d[m][3],
                          ah[m][kc][0], ah[m][kc][1], ah[m][kc][2], ah[m][kc][3],
                          Mf[kc][nb][0], Mf[kc][nb][1]);
                }
#pragma unroll
            for (int m = 0; m < 2; m++) {
                p[m][0] = fmaf(fmaxf(d[m][0], 0.f), mwv[2 * nb],
                          fmaf(fmaxf(d[m][1], 0.f), mwv[2 * nb + 1], p[m][0]));
                p[m][1] = fmaf(fmaxf(d[m][2], 0.f), mwv[2 * nb],
                          fmaf(fmaxf(d[m][3], 0.f), mwv[2 * nb + 1], p[m][1]));
            }
        }
#pragma unroll
        for (int m = 0; m < 2; m++) {
            p[m][0] += __shfl_xor_sync(0xffffffffu, p[m][0], 1);
            p[m][0] += __shfl_xor_sync(0xffffffffu, p[m][0], 2);
            p[m][1] += __shfl_xor_sync(0xffffffffu, p[m][1], 1);
            p[m][1] += __shfl_xor_sync(0xffffffffu, p[m][1], 2);
        }
        if (tg == 0) {
#pragma unroll
            for (int m = 0; m < 2; m++) {
                int r = m * 16 + grp;
                if (r < valid)     mask_out[base + r]     = p[m][0] + mb2v;
                if (r + 8 < valid) mask_out[base + r + 8] = p[m][1] + mb2v;
            }
        }

        // --- pooled (lane = channel) ---
        if (full && SB[0] == SB[TP - 1]) {
            int b = SB[0];
            if (b != cur_b) {
                if (cur_b >= 0) {
                    atomicAdd(&g_pool[cur_b * C + lane], pacc);
                    if (lane == 0) atomicAdd(&g_cnt[cur_b], (float)pcnt);
                }
                cur_b = b; pacc = 0.f; pcnt = 0;
            }
            float a = 0.f;
#pragma unroll
            for (int pnt = 0; pnt < TP; pnt++) a += SX[pnt * XP + lane];
            pacc += a; pcnt += TP;
        } else {
            for (int pnt = 0; pnt < valid; pnt++) {
                int b = SB[pnt];
                if (b != cur_b) {
                    if (cur_b >= 0) {
                        atomicAdd(&g_pool[cur_b * C + lane], pacc);
                        if (lane == 0) atomicAdd(&g_cnt[cur_b], (float)pcnt);
                    }
                    cur_b = b; pacc = 0.f; pcnt = 0;
                }
                pacc += SX[pnt * XP + lane];
                pcnt++;
            }
        }
        __syncwarp();
    }

    if (cur_b >= 0) {
        atomicAdd(&g_pool[cur_b * C + lane], pacc);
        if (lane == 0) atomicAdd(&g_cnt[cur_b], (float)pcnt);
    }
#pragma unroll
    for (int i = 0; i < 8; i++) {
#pragma unroll
        for (int o = 4; o < 32; o <<= 1) {
            s[i]  += __shfl_xor_sync(0xffffffffu, s[i],  o);
            s2[i] += __shfl_xor_sync(0xffffffffu, s2[i], o);
        }
    }
    if (grp == 0) {
#pragma unroll
        for (int i = 0; i < 8; i++) {
            int ch = CH(i, tg);
            atomicAdd(&g_sumH[ch],  s[i]);
            atomicAdd(&g_sumH2[ch], s2[i]);
        }
    }
}

// ================= FINALIZE =================
__global__ void finalize_kernel(
    const float* __restrict__ w1, const float* __restrict__ b1,
    const float* __restrict__ gamma, const float* __restrict__ beta,
    const float* __restrict__ iou_w, const float* __restrict__ iou_b,
    float* __restrict__ out_pooled, float* __restrict__ out_iou,
    int n, int B)
{
    int t = threadIdx.x;
    float inv = 1.f / (float)n;
    float mu  = g_sumH[t] * inv;
    float var = g_sumH2[t] * inv - mu * mu;
    float sc  = gamma[t] * rsqrtf(var + 1e-4f);
    g_b1f[t] = beta[t] + (b1[t] - mu) * sc;
#pragma unroll
    for (int k = 0; k < C; k++) g_w1f[k * C + t] = w1[k * C + t] * sc;

    float iw = iou_w[t];
    for (int b = 0; b < B; b++) {
        float cnt = fmaxf(g_cnt[b], 1.f);
        float pm  = g_pool[b * C + t] / cnt;
        out_pooled[b * C + t] = pm;
        float v = pm * iw;
#pragma unroll
        for (int o = 16; o > 0; o >>= 1) v += __shfl_xor_sync(0xffffffffu, v, o);
        if (t == 0) out_iou[b] = v + iou_b[0];
    }
}

// ================= PASS 2 =================
__global__ void __launch_bounds__(32 * WPB, 4) pass2_kernel(
    const float* __restrict__ feats,
    const float* __restrict__ w2, const float* __restrict__ ob2,
    float* __restrict__ off_out, int n, int tiles_total, int tpw)
{
    __shared__ float sx[WPB][TP * XP];

    const int lane = threadIdx.x & 31;
    const int wi   = threadIdx.x >> 5;
    const int tg   = lane & 3;
    const int grp  = lane >> 2;

    u32 Wf[2][4][2];
#pragma unroll
    for (int kc = 0; kc < 2; kc++)
#pragma unroll
        for (int nb = 0; nb < 4; nb++) {
            int col = nb * 8 + grp;
            int k0 = kc * 16 + 2 * tg;
            Wf[kc][nb][0] = packh2(g_w1f[k0 * C + col],       g_w1f[(k0 + 1) * C + col]);
            Wf[kc][nb][1] = packh2(g_w1f[(k0 + 8) * C + col], g_w1f[(k0 + 9) * C + col]);
        }
    float fb[8], w2v0[8], w2v1[8], w2v2[8];
#pragma unroll
    for (int i = 0; i < 8; i++) {
        int ch = CH(i, tg);
        fb[i]   = g_b1f[ch];
        w2v0[i] = w2[ch * 3 + 0];
        w2v1[i] = w2[ch * 3 + 1];
        w2v2[i] = w2[ch * 3 + 2];
    }
    const float c0 = ob2[0], c1 = ob2[1], c2 = ob2[2];

    const int gwid = blockIdx.x * WPB + wi;
    int t0 = gwid * tpw;
    int t1 = t0 + tpw; if (t1 > tiles_total) t1 = tiles_total;

    float* SX = sx[wi];

    for (int tile = t0; tile < t1; tile++) {
        const int base = tile * TP;
        int valid = n - base; if (valid > TP) valid = TP;
        const int lim = valid * 8;
        const float4* src = (const float4*)(feats + (size_t)base * C);
#pragma unroll
        for (int j = 0; j < 8; j++) {
            int L = lane + 32 * j;
            float4 v = make_float4(0.f, 0.f, 0.f, 0.f);
            if (L < lim) v = src[L];
            *(float4*)&SX[(L >> 3) * XP + 4 * (L & 7)] = v;
        }
        __syncwarp();

        u32 ah[2][2][4], al[2][2][4];
#pragma unroll
        for (int m = 0; m < 2; m++)
#pragma unroll
            for (int kc = 0; kc < 2; kc++)
                load_afrag(SX, m, kc, grp, tg, ah[m][kc], al[m][kc]);

        float o0[2][2], o1[2][2], o2[2][2];
#pragma unroll
        for (int m = 0; m < 2; m++)
#pragma unroll
            for (int r = 0; r < 2; r++) { o0[m][r] = 0.f; o1[m][r] = 0.f; o2[m][r] = 0.f; }

#pragma unroll
        for (int nb = 0; nb < 4; nb++) {
            float d[2][4];
#pragma unroll
            for (int m = 0; m < 2; m++) {
                d[m][0] = fb[2 * nb]; d[m][1] = fb[2 * nb + 1];
                d[m][2] = fb[2 * nb]; d[m][3] = fb[2 * nb + 1];
            }
#pragma unroll
            for (int kc = 0; kc < 2; kc++)
#pragma unroll
                for (int m = 0; m < 2; m++) {
                    MMA16(d[m][0], d[m][1], d[m][2], d[m][3],
                          al[m][kc][0], al[m][kc][1], al[m][kc][2], al[m][kc][3],
                          Wf[kc][nb][0], Wf[kc][nb][1]);
                    MMA16(d[m][0], d[m][1], d[m][2], d[m][3],
                          ah[m][kc][0], ah[m][kc][1], ah[m][kc][2], ah[m][kc][3],
                          Wf[kc][nb][0], Wf[kc][nb][1]);
                }
#pragma unroll
            for (int m = 0; m < 2; m++) {
                float e0 = fmaxf(d[m][0], 0.f), e1 = fmaxf(d[m][1], 0.f);
                float e2 = fmaxf(d[m][2], 0.f), e3 = fmaxf(d[m][3], 0.f);
                o0[m][0] = fmaf(e0, w2v0[2 * nb], fmaf(e1, w2v0[2 * nb + 1], o0[m][0]));
                o1[m][0] = fmaf(e0, w2v1[2 * nb], fmaf(e1, w2v1[2 * nb + 1], o1[m][0]));
                o2[m][0] = fmaf(e0, w2v2[2 * nb], fmaf(e1, w2v2[2 * nb + 1], o2[m][0]));
                o0[m][1] = fmaf(e2, w2v0[2 * nb], fmaf(e3, w2v0[2 * nb + 1], o0[m][1]));
                o1[m][1] = fmaf(e2, w2v1[2 * nb], fmaf(e3, w2v1[2 * nb + 1], o1[m][1]));
                o2[m][1] = fmaf(e2, w2v2[2 * nb], fmaf(e3, w2v2[2 * nb + 1], o2[m][1]));
            }
        }
#pragma unroll
        for (int m = 0; m < 2; m++)
#pragma unroll
            for (int r = 0; r < 2; r++) {
#pragma unroll
                for (int o = 1; o <= 2; o <<= 1) {
                    o0[m][r] += __shfl_xor_sync(0xffffffffu, o0[m][r], o);
                    o1[m][r] += __shfl_xor_sync(0xffffffffu, o1[m][r], o);
                    o2[m][r] += __shfl_xor_sync(0xffffffffu, o2[m][r], o);
                }
            }
        if (tg == 0) {
#pragma unroll
            for (int m = 0; m < 2; m++) {
#pragma unroll
                for (int r = 0; r < 2; r++) {
                    int row = m * 16 + grp + r * 8;
                    if (row < valid) {
                        size_t o = (size_t)(base + row) * 3;
                        off_out[o + 0] = o0[m][r] + c0;
                        off_out[o + 1] = o1[m][r] + c1;
                        off_out[o + 2] = o2[m][r] + c2;
                    }
                }
            }
        }
        __syncwarp();
    }
}

// ================= LAUNCH =================
extern "C" void kernel_launch(void* const* d_in, const int* in_sizes, int n_in,
                              void* d_out, int out_size) {
    const float* feats = (const float*)d_in[0];
    const int*   bidx  = (const int*)  d_in[1];
    const float* w1    = (const float*)d_in[2];
    const float* b1    = (const float*)d_in[3];
    const float* gamma = (const float*)d_in[4];
    const float* beta  = (const float*)d_in[5];
    const float* w2    = (const float*)d_in[6];
    const float* ob2   = (const float*)d_in[7];
    const float* mw1   = (const float*)d_in[8];
    const float* mb1   = (const float*)d_in[9];
    const float* mw2   = (const float*)d_in[10];
    const float* mb2   = (const float*)d_in[11];
    const float* iw    = (const float*)d_in[12];
    const float* ib    = (const float*)d_in[13];

    int n = in_sizes[1];
    int B = (out_size - 4 * n) / 33;
    if (B < 1) B = 1;
    if (B > 64) B = 64;

    float* out        = (float*)d_out;
    float* out_off    = out;
    float* out_mask   = out + (size_t)3 * n;
    float* out_pooled = out + (size_t)4 * n;
    float* out_iou    = out_pooled + (size_t)B * C;

    int tiles  = (n + TP - 1) / TP;
    int blocks = 608;
    int warps  = blocks * WPB;
    int tpw    = (tiles + warps - 1) / warps;

    zero_kernel<<<1, 1024>>>(B);
    pass1_kernel<<<blocks, 32 * WPB>>>(feats, bidx, w1, b1, mw1, mb1, mw2, mb2,
                                       out_mask, n, tiles, tpw);
    finalize_kernel<<<1, 32>>>(w1, b1, gamma, beta, iw, ib,
                               out_pooled, out_iou, n, B);
    pass2_kernel<<<blocks, 32 * WPB>>>(feats, w2, ob2, out_off, n, tiles, tpw);
}